// round 1
// baseline (speedup 1.0000x reference)
#include <cuda_runtime.h>
#include <cstdint>

#define DN 50000
#define DE 800000
#define DT 8

// ---------------- scratch (device globals; no allocation allowed) ----------------
__device__ float g_xt  [DN * 64];    // node GRU final hidden
__device__ float g_y1  [DN * 128];   // (xt @ W1) * dinv
__device__ float g_acc1[DN * 128];   // layer-1 scatter accumulator
__device__ float g_h   [DN * 128];   // relu(layer1)
__device__ float g_y2  [DN * 64];    // (h @ W2) * dinv
__device__ float g_acc2[DN * 64];    // layer-2 scatter accumulator
__device__ float g_dinv[DN];
__device__ int   g_deg [DN];

// ---------------- helpers ----------------
__device__ __forceinline__ float2 ffma2(float2 a, float2 b, float2 c) {
    union { float2 f; unsigned long long u; } A, B, C, D;
    A.f = a; B.f = b; C.f = c;
    asm("fma.rn.f32x2 %0, %1, %2, %3;" : "=l"(D.u) : "l"(A.u), "l"(B.u), "l"(C.u));
    return D.f;
}

__device__ __forceinline__ float sigf(float x) {
    return __fdividef(1.f, 1.f + __expf(-x));
}
__device__ __forceinline__ float tanhfast(float x) {
    x = fminf(15.f, fmaxf(-15.f, x));
    float e = __expf(2.f * x);
    return __fdividef(e - 1.f, e + 1.f);
}

__device__ __forceinline__ void red4(float* p, float4 v) {
    asm volatile("red.global.add.v4.f32 [%0], {%1,%2,%3,%4};"
                 :: "l"(p), "f"(v.x), "f"(v.y), "f"(v.z), "f"(v.w) : "memory");
}

// ---------------- node GRU: one thread per node, weights in shared ----------------
// shared: Wih[192][64] + Whh[192][64] as float4 + biases = 99840 B (dynamic)
__global__ __launch_bounds__(128, 2)
void node_gru_kernel(const float* __restrict__ seq,
                     const float* __restrict__ Wih, const float* __restrict__ Whh,
                     const float* __restrict__ bih, const float* __restrict__ bhh)
{
    extern __shared__ float4 smem[];
    float4* sWih = smem;              // 192*16
    float4* sWhh = smem + 3072;       // 192*16
    float*  sbih = (float*)(smem + 6144);
    float*  sbhh = sbih + 192;
    const int tid = threadIdx.x;
    for (int i = tid; i < 3072; i += 128) {
        sWih[i] = ((const float4*)Wih)[i];
        sWhh[i] = ((const float4*)Whh)[i];
    }
    for (int i = tid; i < 192; i += 128) { sbih[i] = bih[i]; sbhh[i] = bhh[i]; }
    __syncthreads();

    for (int n = blockIdx.x * 128 + tid; n < DN; n += gridDim.x * 128) {
        float2 h2[32];
        #pragma unroll
        for (int k = 0; k < 32; k++) h2[k] = make_float2(0.f, 0.f);
        const float4* xp = (const float4*)(seq + (size_t)n * (DT * 64));
        float zl[64], nl[64];   // local mem (dynamic j index) — cheap vs FMA work
        #pragma unroll 1
        for (int t = 0; t < DT; t++) {
            float2 x2[32];
            #pragma unroll
            for (int i = 0; i < 16; i++) {
                float4 v = xp[t * 16 + i];
                x2[2*i]   = make_float2(v.x, v.y);
                x2[2*i+1] = make_float2(v.z, v.w);
            }
            #pragma unroll 1
            for (int j = 0; j < 64; j++) {
                float2 aR = make_float2(sbih[j]      + sbhh[j],      0.f);
                float2 aZ = make_float2(sbih[64 + j] + sbhh[64 + j], 0.f);
                float2 aI = make_float2(sbih[128 + j], 0.f);
                float2 aH = make_float2(sbhh[128 + j], 0.f);
                const float4* wiR = sWih + j * 16;
                const float4* wiZ = sWih + (64 + j) * 16;
                const float4* wiN = sWih + (128 + j) * 16;
                const float4* whR = sWhh + j * 16;
                const float4* whZ = sWhh + (64 + j) * 16;
                const float4* whN = sWhh + (128 + j) * 16;
                #pragma unroll
                for (int k = 0; k < 16; k++) {
                    float4 wr = wiR[k], wz = wiZ[k], wn = wiN[k];
                    float4 vr = whR[k], vz = whZ[k], vn = whN[k];
                    aR = ffma2(make_float2(wr.x, wr.y), x2[2*k],   aR);
                    aR = ffma2(make_float2(wr.z, wr.w), x2[2*k+1], aR);
                    aZ = ffma2(make_float2(wz.x, wz.y), x2[2*k],   aZ);
                    aZ = ffma2(make_float2(wz.z, wz.w), x2[2*k+1], aZ);
                    aI = ffma2(make_float2(wn.x, wn.y), x2[2*k],   aI);
                    aI = ffma2(make_float2(wn.z, wn.w), x2[2*k+1], aI);
                    aR = ffma2(make_float2(vr.x, vr.y), h2[2*k],   aR);
                    aR = ffma2(make_float2(vr.z, vr.w), h2[2*k+1], aR);
                    aZ = ffma2(make_float2(vz.x, vz.y), h2[2*k],   aZ);
                    aZ = ffma2(make_float2(vz.z, vz.w), h2[2*k+1], aZ);
                    aH = ffma2(make_float2(vn.x, vn.y), h2[2*k],   aH);
                    aH = ffma2(make_float2(vn.z, vn.w), h2[2*k+1], aH);
                }
                float r  = sigf(aR.x + aR.y);
                float z  = sigf(aZ.x + aZ.y);
                float nn = tanhfast(aI.x + aI.y + r * (aH.x + aH.y));
                zl[j] = z; nl[j] = nn;
            }
            #pragma unroll
            for (int k = 0; k < 32; k++) {
                h2[k].x = (1.f - zl[2*k])   * nl[2*k]   + zl[2*k]   * h2[k].x;
                h2[k].y = (1.f - zl[2*k+1]) * nl[2*k+1] + zl[2*k+1] * h2[k].y;
            }
        }
        float4* outp = (float4*)(g_xt + (size_t)n * 64);
        #pragma unroll
        for (int k = 0; k < 16; k++)
            outp[k] = make_float4(h2[2*k].x, h2[2*k].y, h2[2*k+1].x, h2[2*k+1].y);
    }
}

// ---------------- edge GRU + linear decoder: one thread per edge ----------------
__global__ __launch_bounds__(256)
void edge_gru_kernel(const float* __restrict__ seq,
                     const float* __restrict__ Wih, const float* __restrict__ Whh,
                     const float* __restrict__ bih, const float* __restrict__ bhh,
                     const float* __restrict__ Wf,  const float* __restrict__ bf,
                     float* __restrict__ out)
{
    __shared__ float4 sWih[192], sWhh[192], sWf[64];
    __shared__ float  sbih[48], sbhh[48], sbf[16];
    const int tid = threadIdx.x;
    if (tid < 192) { sWih[tid] = ((const float4*)Wih)[tid]; sWhh[tid] = ((const float4*)Whh)[tid]; }
    if (tid < 64)  sWf[tid] = ((const float4*)Wf)[tid];
    if (tid < 48)  { sbih[tid] = bih[tid]; sbhh[tid] = bhh[tid]; }
    if (tid < 16)  sbf[tid] = bf[tid];
    __syncthreads();

    const int e = blockIdx.x * 256 + tid;
    if (e >= DE) return;
    const float4* xp = (const float4*)(seq + (size_t)e * (DT * 16));
    float2 h2[8];
    #pragma unroll
    for (int k = 0; k < 8; k++) h2[k] = make_float2(0.f, 0.f);

    #pragma unroll 1
    for (int t = 0; t < DT; t++) {
        float2 x2[8];
        #pragma unroll
        for (int i = 0; i < 4; i++) {
            float4 v = xp[t * 4 + i];
            x2[2*i] = make_float2(v.x, v.y); x2[2*i+1] = make_float2(v.z, v.w);
        }
        float hn[16], zz[16];
        #pragma unroll
        for (int j = 0; j < 16; j++) {
            float2 aR = make_float2(sbih[j]      + sbhh[j],      0.f);
            float2 aZ = make_float2(sbih[16 + j] + sbhh[16 + j], 0.f);
            float2 aI = make_float2(sbih[32 + j], 0.f);
            float2 aH = make_float2(sbhh[32 + j], 0.f);
            #pragma unroll
            for (int k = 0; k < 4; k++) {
                float4 wr = sWih[j*4 + k], wz = sWih[(16+j)*4 + k], wn = sWih[(32+j)*4 + k];
                float4 vr = sWhh[j*4 + k], vz = sWhh[(16+j)*4 + k], vn = sWhh[(32+j)*4 + k];
                aR = ffma2(make_float2(wr.x, wr.y), x2[2*k],   aR);
                aR = ffma2(make_float2(wr.z, wr.w), x2[2*k+1], aR);
                aZ = ffma2(make_float2(wz.x, wz.y), x2[2*k],   aZ);
                aZ = ffma2(make_float2(wz.z, wz.w), x2[2*k+1], aZ);
                aI = ffma2(make_float2(wn.x, wn.y), x2[2*k],   aI);
                aI = ffma2(make_float2(wn.z, wn.w), x2[2*k+1], aI);
                aR = ffma2(make_float2(vr.x, vr.y), h2[2*k],   aR);
                aR = ffma2(make_float2(vr.z, vr.w), h2[2*k+1], aR);
                aZ = ffma2(make_float2(vz.x, vz.y), h2[2*k],   aZ);
                aZ = ffma2(make_float2(vz.z, vz.w), h2[2*k+1], aZ);
                aH = ffma2(make_float2(vn.x, vn.y), h2[2*k],   aH);
                aH = ffma2(make_float2(vn.z, vn.w), h2[2*k+1], aH);
            }
            float r = sigf(aR.x + aR.y);
            zz[j]   = sigf(aZ.x + aZ.y);
            hn[j]   = tanhfast(aI.x + aI.y + r * (aH.x + aH.y));
        }
        #pragma unroll
        for (int k = 0; k < 8; k++) {
            h2[k].x = (1.f - zz[2*k])   * hn[2*k]   + zz[2*k]   * h2[k].x;
            h2[k].y = (1.f - zz[2*k+1]) * hn[2*k+1] + zz[2*k+1] * h2[k].y;
        }
    }
    // decoder: e_rec[j] = sum_k h[k] * Wf[j][k] + bf[j]
    float4* op = (float4*)(out + (size_t)e * 16);
    #pragma unroll
    for (int j4 = 0; j4 < 4; j4++) {
        float v[4];
        #pragma unroll
        for (int jj = 0; jj < 4; jj++) {
            int j = j4 * 4 + jj;
            float2 a = make_float2(sbf[j], 0.f);
            #pragma unroll
            for (int k = 0; k < 4; k++) {
                float4 w = sWf[j * 4 + k];
                a = ffma2(make_float2(w.x, w.y), h2[2*k],   a);
                a = ffma2(make_float2(w.z, w.w), h2[2*k+1], a);
            }
            v[jj] = a.x + a.y;
        }
        op[j4] = make_float4(v[0], v[1], v[2], v[3]);
    }
}

// ---------------- GCN pipeline ----------------
__global__ void zero_kernel() {
    int idx = blockIdx.x * blockDim.x + threadIdx.x;
    int stride = gridDim.x * blockDim.x;
    for (int i = idx; i < DN * 128; i += stride) g_acc1[i] = 0.f;
    for (int i = idx; i < DN * 64;  i += stride) g_acc2[i] = 0.f;
    for (int i = idx; i < DN;       i += stride) g_deg[i] = 0;
}

__global__ void deg_kernel(const int* __restrict__ dst) {
    int e = blockIdx.x * blockDim.x + threadIdx.x;
    if (e < DE) atomicAdd(&g_deg[dst[e]], 1);
}

__global__ void dinv_kernel() {
    int n = blockIdx.x * blockDim.x + threadIdx.x;
    if (n < DN) g_dinv[n] = rsqrtf((float)(g_deg[n] + 1));  // +1 self-loop
}

// y1 = (xt @ W1) * dinv   [50k x 64] @ [64 x 128]
__global__ __launch_bounds__(128)
void xw1_kernel(const float* __restrict__ W1) {
    __shared__ float4 sW[2048];            // W1 [64][128]
    const int tid = threadIdx.x;
    for (int i = tid; i < 2048; i += 128) sW[i] = ((const float4*)W1)[i];
    __syncthreads();
    int n = blockIdx.x * 128 + tid;
    if (n >= DN) return;
    float2 x2[32];
    const float4* xp = (const float4*)(g_xt + (size_t)n * 64);
    #pragma unroll
    for (int i = 0; i < 16; i++) {
        float4 v = xp[i];
        x2[2*i] = make_float2(v.x, v.y); x2[2*i+1] = make_float2(v.z, v.w);
    }
    float dv = g_dinv[n];
    float4* yp = (float4*)(g_y1 + (size_t)n * 128);
    #pragma unroll 1
    for (int j4 = 0; j4 < 32; j4++) {
        float2 aA = make_float2(0.f, 0.f), aB = make_float2(0.f, 0.f);
        #pragma unroll
        for (int k = 0; k < 64; k++) {
            float4 w = sW[k * 32 + j4];
            float xk = (k & 1) ? x2[k >> 1].y : x2[k >> 1].x;
            float2 xs = make_float2(xk, xk);
            aA = ffma2(xs, make_float2(w.x, w.y), aA);
            aB = ffma2(xs, make_float2(w.z, w.w), aB);
        }
        yp[j4] = make_float4(aA.x * dv, aA.y * dv, aB.x * dv, aB.y * dv);
    }
}

// y2 = (h @ W2) * dinv   [50k x 128] @ [128 x 64]
__global__ __launch_bounds__(128, 2)
void xw2_kernel(const float* __restrict__ W2) {
    __shared__ float4 sW[2048];            // W2 [128][64]
    const int tid = threadIdx.x;
    for (int i = tid; i < 2048; i += 128) sW[i] = ((const float4*)W2)[i];
    __syncthreads();
    int n = blockIdx.x * 128 + tid;
    if (n >= DN) return;
    float2 x2[64];
    const float4* xp = (const float4*)(g_h + (size_t)n * 128);
    #pragma unroll
    for (int i = 0; i < 32; i++) {
        float4 v = xp[i];
        x2[2*i] = make_float2(v.x, v.y); x2[2*i+1] = make_float2(v.z, v.w);
    }
    float dv = g_dinv[n];
    float4* yp = (float4*)(g_y2 + (size_t)n * 64);
    #pragma unroll 1
    for (int j4 = 0; j4 < 16; j4++) {
        float2 aA = make_float2(0.f, 0.f), aB = make_float2(0.f, 0.f);
        #pragma unroll
        for (int k = 0; k < 128; k++) {
            float4 w = sW[k * 16 + j4];
            float xk = (k & 1) ? x2[k >> 1].y : x2[k >> 1].x;
            float2 xs = make_float2(xk, xk);
            aA = ffma2(xs, make_float2(w.x, w.y), aA);
            aB = ffma2(xs, make_float2(w.z, w.w), aB);
        }
        yp[j4] = make_float4(aA.x * dv, aA.y * dv, aB.x * dv, aB.y * dv);
    }
}

__global__ void scatter1_kernel(const int* __restrict__ src, const int* __restrict__ dst) {
    int idx = blockIdx.x * blockDim.x + threadIdx.x;   // warp per edge: 32 float4 per edge
    if (idx >= DE * 32) return;
    int e = idx >> 5, c = idx & 31;
    int s = src[e], d = dst[e];
    float4 v = ((const float4*)g_y1)[(size_t)s * 32 + c];
    red4(&g_acc1[(size_t)d * 128 + c * 4], v);
}

__global__ void scatter2_kernel(const int* __restrict__ src, const int* __restrict__ dst) {
    int idx = blockIdx.x * blockDim.x + threadIdx.x;   // 16 float4 per edge
    if (idx >= DE * 16) return;
    int e = idx >> 4, c = idx & 15;
    int s = src[e], d = dst[e];
    float4 v = ((const float4*)g_y2)[(size_t)s * 16 + c];
    red4(&g_acc2[(size_t)d * 64 + c * 4], v);
}

__global__ void fin1_kernel(const float* __restrict__ b1) {
    int idx = blockIdx.x * blockDim.x + threadIdx.x;   // DN*32 float4
    if (idx >= DN * 32) return;
    int n = idx >> 5, c = idx & 31;
    float dv = g_dinv[n];
    float4 a = ((const float4*)g_acc1)[idx];
    float4 y = ((const float4*)g_y1)[idx];
    float4 b = ((const float4*)b1)[c];
    float4 r;
    r.x = fmaxf(dv * (a.x + y.x) + b.x, 0.f);
    r.y = fmaxf(dv * (a.y + y.y) + b.y, 0.f);
    r.z = fmaxf(dv * (a.z + y.z) + b.z, 0.f);
    r.w = fmaxf(dv * (a.w + y.w) + b.w, 0.f);
    ((float4*)g_h)[idx] = r;
}

__global__ void fin2_kernel(const float* __restrict__ b2, float* __restrict__ out) {
    int idx = blockIdx.x * blockDim.x + threadIdx.x;   // DN*16 float4
    if (idx >= DN * 16) return;
    int n = idx >> 4, c = idx & 15;
    float dv = g_dinv[n];
    float4 a = ((const float4*)g_acc2)[idx];
    float4 y = ((const float4*)g_y2)[idx];
    float4 b = ((const float4*)b2)[c];
    float4 r;
    r.x = dv * (a.x + y.x) + b.x;
    r.y = dv * (a.y + y.y) + b.y;
    r.z = dv * (a.z + y.z) + b.z;
    r.w = dv * (a.w + y.w) + b.w;
    ((float4*)out)[idx] = r;
}

// ---------------- launch ----------------
extern "C" void kernel_launch(void* const* d_in, const int* in_sizes, int n_in,
                              void* d_out, int out_size)
{
    const float* node_seq = (const float*)d_in[0];
    const float* edge_seq = (const float*)d_in[1];
    const int*   eidx     = (const int*)d_in[2];
    const float* Wihn = (const float*)d_in[3];
    const float* Whhn = (const float*)d_in[4];
    const float* bihn = (const float*)d_in[5];
    const float* bhhn = (const float*)d_in[6];
    const float* Wihe = (const float*)d_in[7];
    const float* Whhe = (const float*)d_in[8];
    const float* bihe = (const float*)d_in[9];
    const float* bhhe = (const float*)d_in[10];
    const float* W1   = (const float*)d_in[11];
    const float* b1   = (const float*)d_in[12];
    const float* W2   = (const float*)d_in[13];
    const float* b2   = (const float*)d_in[14];
    const float* Wf   = (const float*)d_in[15];
    const float* bf   = (const float*)d_in[16];
    float* out = (float*)d_out;
    const int* src = eidx;
    const int* dst = eidx + DE;

    cudaFuncSetAttribute(node_gru_kernel,
                         cudaFuncAttributeMaxDynamicSharedMemorySize, 99840);

    zero_kernel<<<2048, 256>>>();
    node_gru_kernel<<<296, 128, 99840>>>(node_seq, Wihn, Whhn, bihn, bhhn);
    deg_kernel<<<(DE + 255) / 256, 256>>>(dst);
    dinv_kernel<<<(DN + 255) / 256, 256>>>();
    xw1_kernel<<<(DN + 127) / 128, 128>>>(W1);
    scatter1_kernel<<<(DE * 32 + 255) / 256, 256>>>(src, dst);
    fin1_kernel<<<(DN * 32 + 255) / 256, 256>>>(b1);
    xw2_kernel<<<(DN + 127) / 128, 128>>>(W2);
    scatter2_kernel<<<(DE * 16 + 255) / 256, 256>>>(src, dst);
    fin2_kernel<<<(DN * 16 + 255) / 256, 256>>>(b2, out);
    edge_gru_kernel<<<DE / 256, 256>>>(edge_seq, Wihe, Whhe, bihe, bhhe, Wf, bf,
                                       out + (size_t)DN * 64);
}

// round 2
// speedup vs baseline: 4.3656x; 4.3656x over previous
#include <cuda_runtime.h>
#include <cstdint>

#define DN 50000
#define DE 800000
#define DT 8

// ---------------- scratch (device globals; no allocation allowed) ----------------
__device__ float g_xt  [DN * 64];    // node GRU final hidden
__device__ float g_y1  [DN * 128];   // (xt @ W1) * dinv
__device__ float g_acc1[DN * 128];   // layer-1 scatter accumulator
__device__ float g_h   [DN * 128];   // relu(layer1)
__device__ float g_y2  [DN * 64];    // (h @ W2) * dinv
__device__ float g_acc2[DN * 64];    // layer-2 scatter accumulator
__device__ float g_dinv[DN];
__device__ int   g_deg [DN];

// ---------------- helpers ----------------
__device__ __forceinline__ float sigf(float x) {
    return __fdividef(1.f, 1.f + __expf(-x));
}
__device__ __forceinline__ float tanhfast(float x) {
    x = fminf(15.f, fmaxf(-15.f, x));
    float e = __expf(2.f * x);
    return __fdividef(e - 1.f, e + 1.f);
}
__device__ __forceinline__ void red4(float* p, float4 v) {
    asm volatile("red.global.add.v4.f32 [%0], {%1,%2,%3,%4};"
                 :: "l"(p), "f"(v.x), "f"(v.y), "f"(v.z), "f"(v.w) : "memory");
}

// ---------------- node GRU: one thread per node, weights in shared ----------------
__global__ __launch_bounds__(128, 2)
void node_gru_kernel(const float* __restrict__ seq,
                     const float* __restrict__ Wih, const float* __restrict__ Whh,
                     const float* __restrict__ bih, const float* __restrict__ bhh)
{
    extern __shared__ float4 smem[];
    float4* sWih = smem;              // 192 rows x 16 float4
    float4* sWhh = smem + 3072;
    float*  sbih = (float*)(smem + 6144);
    float*  sbhh = sbih + 192;
    const int tid = threadIdx.x;
    for (int i = tid; i < 3072; i += 128) {
        sWih[i] = ((const float4*)Wih)[i];
        sWhh[i] = ((const float4*)Whh)[i];
    }
    for (int i = tid; i < 192; i += 128) { sbih[i] = bih[i]; sbhh[i] = bhh[i]; }
    __syncthreads();

    const int n = blockIdx.x * 128 + tid;
    if (n >= DN) return;

    float h[64];
    #pragma unroll
    for (int k = 0; k < 64; k++) h[k] = 0.f;
    const float4* xp = (const float4*)(seq + (size_t)n * (DT * 64));
    float zl[64], nl[64];   // dynamic-j writes -> local mem; ~2% of FFMA cost

    #pragma unroll 1
    for (int t = 0; t < DT; t++) {
        float x[64];
        #pragma unroll
        for (int i = 0; i < 16; i++) {
            float4 v = xp[t * 16 + i];
            x[4*i] = v.x; x[4*i+1] = v.y; x[4*i+2] = v.z; x[4*i+3] = v.w;
        }
        #pragma unroll 1
        for (int j = 0; j < 64; j++) {
            float aR = sbih[j]       + sbhh[j];
            float aZ = sbih[64 + j]  + sbhh[64 + j];
            float aI = sbih[128 + j];
            float aH = sbhh[128 + j];
            const float4* wiR = sWih + j * 16;
            const float4* wiZ = sWih + (64 + j) * 16;
            const float4* wiN = sWih + (128 + j) * 16;
            const float4* whR = sWhh + j * 16;
            const float4* whZ = sWhh + (64 + j) * 16;
            const float4* whN = sWhh + (128 + j) * 16;
            #pragma unroll
            for (int k = 0; k < 16; k++) {
                float4 wr = wiR[k], wz = wiZ[k], wn = wiN[k];
                float4 vr = whR[k], vz = whZ[k], vn = whN[k];
                aR = fmaf(wr.x, x[4*k],   aR); aR = fmaf(wr.y, x[4*k+1], aR);
                aR = fmaf(wr.z, x[4*k+2], aR); aR = fmaf(wr.w, x[4*k+3], aR);
                aZ = fmaf(wz.x, x[4*k],   aZ); aZ = fmaf(wz.y, x[4*k+1], aZ);
                aZ = fmaf(wz.z, x[4*k+2], aZ); aZ = fmaf(wz.w, x[4*k+3], aZ);
                aI = fmaf(wn.x, x[4*k],   aI); aI = fmaf(wn.y, x[4*k+1], aI);
                aI = fmaf(wn.z, x[4*k+2], aI); aI = fmaf(wn.w, x[4*k+3], aI);
                aR = fmaf(vr.x, h[4*k],   aR); aR = fmaf(vr.y, h[4*k+1], aR);
                aR = fmaf(vr.z, h[4*k+2], aR); aR = fmaf(vr.w, h[4*k+3], aR);
                aZ = fmaf(vz.x, h[4*k],   aZ); aZ = fmaf(vz.y, h[4*k+1], aZ);
                aZ = fmaf(vz.z, h[4*k+2], aZ); aZ = fmaf(vz.w, h[4*k+3], aZ);
                aH = fmaf(vn.x, h[4*k],   aH); aH = fmaf(vn.y, h[4*k+1], aH);
                aH = fmaf(vn.z, h[4*k+2], aH); aH = fmaf(vn.w, h[4*k+3], aH);
            }
            float r = sigf(aR);
            zl[j]   = sigf(aZ);
            nl[j]   = tanhfast(aI + r * aH);
        }
        #pragma unroll
        for (int k = 0; k < 64; k++) {
            // h = (1-z)*n + z*h = n + z*(h-n)
            h[k] = fmaf(zl[k], h[k] - nl[k], nl[k]);
        }
    }
    float4* outp = (float4*)(g_xt + (size_t)n * 64);
    #pragma unroll
    for (int k = 0; k < 16; k++)
        outp[k] = make_float4(h[4*k], h[4*k+1], h[4*k+2], h[4*k+3]);
}

// ---------------- edge GRU + linear decoder: one thread per edge ----------------
__global__ __launch_bounds__(256)
void edge_gru_kernel(const float* __restrict__ seq,
                     const float* __restrict__ Wih, const float* __restrict__ Whh,
                     const float* __restrict__ bih, const float* __restrict__ bhh,
                     const float* __restrict__ Wf,  const float* __restrict__ bf,
                     float* __restrict__ out)
{
    __shared__ float4 sWih[192], sWhh[192], sWf[64];
    __shared__ float  sbih[48], sbhh[48], sbf[16];
    const int tid = threadIdx.x;
    if (tid < 192) { sWih[tid] = ((const float4*)Wih)[tid]; sWhh[tid] = ((const float4*)Whh)[tid]; }
    if (tid < 64)  sWf[tid] = ((const float4*)Wf)[tid];
    if (tid < 48)  { sbih[tid] = bih[tid]; sbhh[tid] = bhh[tid]; }
    if (tid < 16)  sbf[tid] = bf[tid];
    __syncthreads();

    const int e = blockIdx.x * 256 + tid;
    if (e >= DE) return;
    const float4* xp = (const float4*)(seq + (size_t)e * (DT * 16));
    float h[16];
    #pragma unroll
    for (int k = 0; k < 16; k++) h[k] = 0.f;

    float zz[16], hn[16];
    #pragma unroll 1
    for (int t = 0; t < DT; t++) {
        float x[16];
        #pragma unroll
        for (int i = 0; i < 4; i++) {
            float4 v = xp[t * 4 + i];
            x[4*i] = v.x; x[4*i+1] = v.y; x[4*i+2] = v.z; x[4*i+3] = v.w;
        }
        #pragma unroll 1
        for (int j = 0; j < 16; j++) {
            float aR = sbih[j]      + sbhh[j];
            float aZ = sbih[16 + j] + sbhh[16 + j];
            float aI = sbih[32 + j];
            float aH = sbhh[32 + j];
            #pragma unroll
            for (int k = 0; k < 4; k++) {
                float4 wr = sWih[j*4 + k], wz = sWih[(16+j)*4 + k], wn = sWih[(32+j)*4 + k];
                float4 vr = sWhh[j*4 + k], vz = sWhh[(16+j)*4 + k], vn = sWhh[(32+j)*4 + k];
                aR = fmaf(wr.x, x[4*k],   aR); aR = fmaf(wr.y, x[4*k+1], aR);
                aR = fmaf(wr.z, x[4*k+2], aR); aR = fmaf(wr.w, x[4*k+3], aR);
                aZ = fmaf(wz.x, x[4*k],   aZ); aZ = fmaf(wz.y, x[4*k+1], aZ);
                aZ = fmaf(wz.z, x[4*k+2], aZ); aZ = fmaf(wz.w, x[4*k+3], aZ);
                aI = fmaf(wn.x, x[4*k],   aI); aI = fmaf(wn.y, x[4*k+1], aI);
                aI = fmaf(wn.z, x[4*k+2], aI); aI = fmaf(wn.w, x[4*k+3], aI);
                aR = fmaf(vr.x, h[4*k],   aR); aR = fmaf(vr.y, h[4*k+1], aR);
                aR = fmaf(vr.z, h[4*k+2], aR); aR = fmaf(vr.w, h[4*k+3], aR);
                aZ = fmaf(vz.x, h[4*k],   aZ); aZ = fmaf(vz.y, h[4*k+1], aZ);
                aZ = fmaf(vz.z, h[4*k+2], aZ); aZ = fmaf(vz.w, h[4*k+3], aZ);
                aH = fmaf(vn.x, h[4*k],   aH); aH = fmaf(vn.y, h[4*k+1], aH);
                aH = fmaf(vn.z, h[4*k+2], aH); aH = fmaf(vn.w, h[4*k+3], aH);
            }
            float r = sigf(aR);
            zz[j]   = sigf(aZ);
            hn[j]   = tanhfast(aI + r * aH);
        }
        #pragma unroll
        for (int k = 0; k < 16; k++)
            h[k] = fmaf(zz[k], h[k] - hn[k], hn[k]);
    }
    // decoder: e_rec[j] = sum_k h[k] * Wf[j][k] + bf[j]
    float4* op = (float4*)(out + (size_t)e * 16);
    #pragma unroll
    for (int j4 = 0; j4 < 4; j4++) {
        float v[4];
        #pragma unroll
        for (int jj = 0; jj < 4; jj++) {
            int j = j4 * 4 + jj;
            float a = sbf[j];
            #pragma unroll
            for (int k = 0; k < 4; k++) {
                float4 w = sWf[j * 4 + k];
                a = fmaf(w.x, h[4*k],   a); a = fmaf(w.y, h[4*k+1], a);
                a = fmaf(w.z, h[4*k+2], a); a = fmaf(w.w, h[4*k+3], a);
            }
            v[jj] = a;
        }
        op[j4] = make_float4(v[0], v[1], v[2], v[3]);
    }
}

// ---------------- GCN pipeline ----------------
__global__ void zero_kernel() {
    int idx = blockIdx.x * blockDim.x + threadIdx.x;
    int stride = gridDim.x * blockDim.x;
    for (int i = idx; i < DN * 128; i += stride) g_acc1[i] = 0.f;
    for (int i = idx; i < DN * 64;  i += stride) g_acc2[i] = 0.f;
    for (int i = idx; i < DN;       i += stride) g_deg[i] = 0;
}

__global__ void deg_kernel(const int* __restrict__ dst) {
    int e = blockIdx.x * blockDim.x + threadIdx.x;
    if (e < DE) atomicAdd(&g_deg[dst[e]], 1);
}

__global__ void dinv_kernel() {
    int n = blockIdx.x * blockDim.x + threadIdx.x;
    if (n < DN) g_dinv[n] = rsqrtf((float)(g_deg[n] + 1));  // +1 self-loop
}

// y1 = (xt @ W1) * dinv   [50k x 64] @ [64 x 128]
__global__ __launch_bounds__(128)
void xw1_kernel(const float* __restrict__ W1) {
    __shared__ float4 sW[2048];            // W1 [64][128]
    const int tid = threadIdx.x;
    for (int i = tid; i < 2048; i += 128) sW[i] = ((const float4*)W1)[i];
    __syncthreads();
    int n = blockIdx.x * 128 + tid;
    if (n >= DN) return;
    float x[64];
    const float4* xp = (const float4*)(g_xt + (size_t)n * 64);
    #pragma unroll
    for (int i = 0; i < 16; i++) {
        float4 v = xp[i];
        x[4*i] = v.x; x[4*i+1] = v.y; x[4*i+2] = v.z; x[4*i+3] = v.w;
    }
    float dv = g_dinv[n];
    float4* yp = (float4*)(g_y1 + (size_t)n * 128);
    #pragma unroll 1
    for (int j4 = 0; j4 < 32; j4++) {
        float a0 = 0.f, a1 = 0.f, a2 = 0.f, a3 = 0.f;
        #pragma unroll
        for (int k = 0; k < 64; k++) {
            float4 w = sW[k * 32 + j4];
            a0 = fmaf(x[k], w.x, a0); a1 = fmaf(x[k], w.y, a1);
            a2 = fmaf(x[k], w.z, a2); a3 = fmaf(x[k], w.w, a3);
        }
        yp[j4] = make_float4(a0 * dv, a1 * dv, a2 * dv, a3 * dv);
    }
}

// y2 = (h @ W2) * dinv   [50k x 128] @ [128 x 64]
__global__ __launch_bounds__(128, 2)
void xw2_kernel(const float* __restrict__ W2) {
    __shared__ float4 sW[2048];            // W2 [128][64]
    const int tid = threadIdx.x;
    for (int i = tid; i < 2048; i += 128) sW[i] = ((const float4*)W2)[i];
    __syncthreads();
    int n = blockIdx.x * 128 + tid;
    if (n >= DN) return;
    float x[128];
    const float4* xp = (const float4*)(g_h + (size_t)n * 128);
    #pragma unroll
    for (int i = 0; i < 32; i++) {
        float4 v = xp[i];
        x[4*i] = v.x; x[4*i+1] = v.y; x[4*i+2] = v.z; x[4*i+3] = v.w;
    }
    float dv = g_dinv[n];
    float4* yp = (float4*)(g_y2 + (size_t)n * 64);
    #pragma unroll 1
    for (int j4 = 0; j4 < 16; j4++) {
        float a0 = 0.f, a1 = 0.f, a2 = 0.f, a3 = 0.f;
        #pragma unroll
        for (int k = 0; k < 128; k++) {
            float4 w = sW[k * 16 + j4];
            a0 = fmaf(x[k], w.x, a0); a1 = fmaf(x[k], w.y, a1);
            a2 = fmaf(x[k], w.z, a2); a3 = fmaf(x[k], w.w, a3);
        }
        yp[j4] = make_float4(a0 * dv, a1 * dv, a2 * dv, a3 * dv);
    }
}

__global__ void scatter1_kernel(const int* __restrict__ src, const int* __restrict__ dst) {
    int idx = blockIdx.x * blockDim.x + threadIdx.x;   // warp per edge: 32 float4 per edge
    if (idx >= DE * 32) return;
    int e = idx >> 5, c = idx & 31;
    int s = src[e], d = dst[e];
    float4 v = ((const float4*)g_y1)[(size_t)s * 32 + c];
    red4(&g_acc1[(size_t)d * 128 + c * 4], v);
}

__global__ void scatter2_kernel(const int* __restrict__ src, const int* __restrict__ dst) {
    int idx = blockIdx.x * blockDim.x + threadIdx.x;   // 16 float4 per edge
    if (idx >= DE * 16) return;
    int e = idx >> 4, c = idx & 15;
    int s = src[e], d = dst[e];
    float4 v = ((const float4*)g_y2)[(size_t)s * 16 + c];
    red4(&g_acc2[(size_t)d * 64 + c * 4], v);
}

__global__ void fin1_kernel(const float* __restrict__ b1) {
    int idx = blockIdx.x * blockDim.x + threadIdx.x;   // DN*32 float4
    if (idx >= DN * 32) return;
    int n = idx >> 5, c = idx & 31;
    float dv = g_dinv[n];
    float4 a = ((const float4*)g_acc1)[idx];
    float4 y = ((const float4*)g_y1)[idx];
    float4 b = ((const float4*)b1)[c];
    float4 r;
    r.x = fmaxf(fmaf(dv, a.x + y.x, b.x), 0.f);
    r.y = fmaxf(fmaf(dv, a.y + y.y, b.y), 0.f);
    r.z = fmaxf(fmaf(dv, a.z + y.z, b.z), 0.f);
    r.w = fmaxf(fmaf(dv, a.w + y.w, b.w), 0.f);
    ((float4*)g_h)[idx] = r;
}

__global__ void fin2_kernel(const float* __restrict__ b2, float* __restrict__ out) {
    int idx = blockIdx.x * blockDim.x + threadIdx.x;   // DN*16 float4
    if (idx >= DN * 16) return;
    int n = idx >> 4, c = idx & 15;
    float dv = g_dinv[n];
    float4 a = ((const float4*)g_acc2)[idx];
    float4 y = ((const float4*)g_y2)[idx];
    float4 b = ((const float4*)b2)[c];
    float4 r;
    r.x = fmaf(dv, a.x + y.x, b.x);
    r.y = fmaf(dv, a.y + y.y, b.y);
    r.z = fmaf(dv, a.z + y.z, b.z);
    r.w = fmaf(dv, a.w + y.w, b.w);
    ((float4*)out)[idx] = r;
}

// ---------------- launch ----------------
extern "C" void kernel_launch(void* const* d_in, const int* in_sizes, int n_in,
                              void* d_out, int out_size)
{
    const float* node_seq = (const float*)d_in[0];
    const float* edge_seq = (const float*)d_in[1];
    const int*   eidx     = (const int*)d_in[2];
    const float* Wihn = (const float*)d_in[3];
    const float* Whhn = (const float*)d_in[4];
    const float* bihn = (const float*)d_in[5];
    const float* bhhn = (const float*)d_in[6];
    const float* Wihe = (const float*)d_in[7];
    const float* Whhe = (const float*)d_in[8];
    const float* bihe = (const float*)d_in[9];
    const float* bhhe = (const float*)d_in[10];
    const float* W1   = (const float*)d_in[11];
    const float* b1   = (const float*)d_in[12];
    const float* W2   = (const float*)d_in[13];
    const float* b2   = (const float*)d_in[14];
    const float* Wf   = (const float*)d_in[15];
    const float* bf   = (const float*)d_in[16];
    float* out = (float*)d_out;
    const int* src = eidx;
    const int* dst = eidx + DE;

    cudaFuncSetAttribute(node_gru_kernel,
                         cudaFuncAttributeMaxDynamicSharedMemorySize, 99840);

    // Order chosen so the ncu -s/-c window (which hit launch #4 last round)
    // lands on a GRU kernel this round.
    zero_kernel<<<2048, 256>>>();
    deg_kernel<<<(DE + 255) / 256, 256>>>(dst);
    dinv_kernel<<<(DN + 255) / 256, 256>>>();
    node_gru_kernel<<<(DN + 127) / 128, 128, 99840>>>(node_seq, Wihn, Whhn, bihn, bhhn);
    edge_gru_kernel<<<(DE + 255) / 256, 256>>>(edge_seq, Wihe, Whhe, bihe, bhhe, Wf, bf,
                                               out + (size_t)DN * 64);
    xw1_kernel<<<(DN + 127) / 128, 128>>>(W1);
    scatter1_kernel<<<(DE * 32 + 255) / 256, 256>>>(src, dst);
    fin1_kernel<<<(DN * 32 + 255) / 256, 256>>>(b1);
    xw2_kernel<<<(DN + 127) / 128, 128>>>(W2);
    scatter2_kernel<<<(DE * 16 + 255) / 256, 256>>>(src, dst);
    fin2_kernel<<<(DN * 16 + 255) / 256, 256>>>(b2, out);
}